// round 1
// baseline (speedup 1.0000x reference)
#include <cuda_runtime.h>
#include <math.h>

#define N_LAYERS 24
#define D_MODEL  768
#define D_INNER  1536
#define D_STATE  16
#define DT_RANK  48
#define CONV_K   4
#define VOCAB    50280
#define SEQ      8
#define BATCH    64
#define NTOK     (BATCH*SEQ)     // 512
#define LFULL    64
#define PROJ_W   (DT_RANK + 2*D_STATE)  // 80

// ---------------- scratch (alloc-free: __device__ globals) ----------------
__device__ float g_h   [NTOK * D_MODEL];
__device__ float g_hn  [NTOK * D_MODEL];
__device__ float g_xz  [NTOK * 2 * D_INNER];
__device__ float g_x   [NTOK * D_INNER];
__device__ float g_proj[NTOK * PROJ_W];
__device__ float g_dt  [NTOK * D_INNER];
__device__ float g_y   [NTOK * D_INNER];

typedef unsigned long long ull;

// ---------------- packed f32x2 helpers ----------------
__device__ __forceinline__ ull pack_dup(float v) {
    ull r; asm("mov.b64 %0, {%1, %1};" : "=l"(r) : "f"(v)); return r;
}
__device__ __forceinline__ void ffma2(ull &d, ull a, ull b) {
    asm("fma.rn.f32x2 %0, %1, %2, %0;" : "+l"(d) : "l"(a), "l"(b));
}
__device__ __forceinline__ float2 unpack2(ull v) {
    float2 r; asm("mov.b64 {%0, %1}, %2;" : "=f"(r.x), "=f"(r.y) : "l"(v)); return r;
}

// ---------------- generic NT GEMM: C[M,N] (+)= A[M,K] * B[N,K]^T ----------------
// Requirements: M % 64 == 0, K % 16 == 0, all leading dims multiples of 4 floats.
#define BM 64
#define BN 64
#define BK 16

__global__ void gemm_nt(const float* __restrict__ A, int lda,
                        const float* __restrict__ B, int ldb,
                        float* __restrict__ C, int ldc,
                        int M, int N, int K, int acc)
{
    __shared__ float As[BK][BM];
    __shared__ float Bs[BK][BN];

    const int tid = threadIdx.x;
    const int tx = tid & 15;        // 0..15 -> N direction (4 cols each)
    const int ty = tid >> 4;        // 0..15 -> M direction (4 rows each)
    const int bm = blockIdx.y * BM;
    const int bn = blockIdx.x * BN;

    ull accr[4][2];
#pragma unroll
    for (int i = 0; i < 4; i++) { accr[i][0] = 0ull; accr[i][1] = 0ull; }

    const int lr = tid >> 2;        // 0..63  (tile row)
    const int lc = (tid & 3) * 4;   // 0,4,8,12 (tile col, float4)

    for (int k0 = 0; k0 < K; k0 += BK) {
        {
            int m = bm + lr;  // M is multiple of 64 -> in bounds
            float4 av = *reinterpret_cast<const float4*>(&A[(size_t)m * lda + k0 + lc]);
            As[lc+0][lr] = av.x; As[lc+1][lr] = av.y; As[lc+2][lr] = av.z; As[lc+3][lr] = av.w;

            int n = bn + lr; if (n >= N) n = N - 1;   // clamp read, store guarded later
            float4 bv = *reinterpret_cast<const float4*>(&B[(size_t)n * ldb + k0 + lc]);
            Bs[lc+0][lr] = bv.x; Bs[lc+1][lr] = bv.y; Bs[lc+2][lr] = bv.z; Bs[lc+3][lr] = bv.w;
        }
        __syncthreads();

#pragma unroll
        for (int k = 0; k < BK; k++) {
            float4 av = *reinterpret_cast<const float4*>(&As[k][ty * 4]);
            const ull* bp = reinterpret_cast<const ull*>(&Bs[k][tx * 4]);
            ull b01 = bp[0], b23 = bp[1];
            ull a0 = pack_dup(av.x), a1 = pack_dup(av.y);
            ull a2 = pack_dup(av.z), a3 = pack_dup(av.w);
            ffma2(accr[0][0], a0, b01); ffma2(accr[0][1], a0, b23);
            ffma2(accr[1][0], a1, b01); ffma2(accr[1][1], a1, b23);
            ffma2(accr[2][0], a2, b01); ffma2(accr[2][1], a2, b23);
            ffma2(accr[3][0], a3, b01); ffma2(accr[3][1], a3, b23);
        }
        __syncthreads();
    }

#pragma unroll
    for (int i = 0; i < 4; i++) {
        int m = bm + ty * 4 + i;
#pragma unroll
        for (int jp = 0; jp < 2; jp++) {
            float2 v = unpack2(accr[i][jp]);
            int n = bn + tx * 4 + jp * 2;
            if (n < N) {
                float* p = &C[(size_t)m * ldc + n];
                if (acc) *p += v.x; else *p = v.x;
            }
            if (n + 1 < N) {
                float* p = &C[(size_t)m * ldc + n + 1];
                if (acc) *p += v.y; else *p = v.y;
            }
        }
    }
}

// ---------------- embedding gather ----------------
__global__ void gather_kernel(const int* __restrict__ ids,
                              const float* __restrict__ embed,
                              float* __restrict__ h)
{
    int tok = blockIdx.x;
    int b = tok / SEQ, t = tok % SEQ;
    int id = ids[b * LFULL + t];
    const float* src = embed + (size_t)id * D_MODEL;
    for (int i = threadIdx.x; i < D_MODEL; i += 256)
        h[(size_t)tok * D_MODEL + i] = src[i];
}

// ---------------- rmsnorm (one block per token) ----------------
__global__ void rmsnorm_kernel(const float* __restrict__ in,
                               const float* __restrict__ w,
                               float* __restrict__ out)
{
    int tok = blockIdx.x;
    __shared__ float red[256];
    const float* row = in + (size_t)tok * D_MODEL;
    float s = 0.f;
    for (int i = threadIdx.x; i < D_MODEL; i += 256) { float v = row[i]; s += v * v; }
    red[threadIdx.x] = s;
    __syncthreads();
    for (int st = 128; st > 0; st >>= 1) {
        if (threadIdx.x < st) red[threadIdx.x] += red[threadIdx.x + st];
        __syncthreads();
    }
    float inv = rsqrtf(red[0] / (float)D_MODEL + 1e-5f);
    for (int i = threadIdx.x; i < D_MODEL; i += 256)
        out[(size_t)tok * D_MODEL + i] = row[i] * inv * w[i];
}

// ---------------- causal depthwise conv (K=4) + bias + silu + mask ----------------
__global__ void conv_kernel(const float* __restrict__ xz,
                            const int* __restrict__ mask,
                            const float* __restrict__ cw,
                            const float* __restrict__ cb,
                            float* __restrict__ xout)
{
    int gid = blockIdx.x * blockDim.x + threadIdx.x;
    if (gid >= NTOK * D_INNER) return;
    int d = gid % D_INNER;
    int tok = gid / D_INNER;
    int b = tok / SEQ, t = tok % SEQ;

    float acc = cb[d];
#pragma unroll
    for (int j = 0; j < CONV_K; j++) {
        int tt = t - (CONV_K - 1) + j;
        if (tt >= 0) {
            float mv = (float)mask[b * LFULL + tt];
            acc += cw[d * CONV_K + j] * xz[(size_t)(b * SEQ + tt) * 2 * D_INNER + d] * mv;
        }
    }
    float s = acc / (1.f + expf(-acc));       // silu
    float mv = (float)mask[b * LFULL + t];
    xout[gid] = s * mv;
}

// ---------------- dt bias + softplus (in place) ----------------
__global__ void dtact_kernel(float* __restrict__ dt, const float* __restrict__ bias)
{
    int gid = blockIdx.x * blockDim.x + threadIdx.x;
    if (gid >= NTOK * D_INNER) return;
    int d = gid % D_INNER;
    float v = dt[gid] + bias[d];
    dt[gid] = (v > 20.f) ? v : log1pf(expf(v));
}

// ---------------- selective scan over T=8 + skip + gate ----------------
__global__ void scan_kernel(const float* __restrict__ x,
                            const float* __restrict__ dt,
                            const float* __restrict__ proj,
                            const float* __restrict__ xz,
                            const float* __restrict__ A_log,
                            const float* __restrict__ Dp,
                            float* __restrict__ y)
{
    int gid = blockIdx.x * blockDim.x + threadIdx.x;
    if (gid >= BATCH * D_INNER) return;
    int d = gid % D_INNER;
    int b = gid / D_INNER;

    float A[D_STATE];
#pragma unroll
    for (int n = 0; n < D_STATE; n++) A[n] = -expf(A_log[d * D_STATE + n]);
    float Dv = Dp[d];

    float h[D_STATE];
#pragma unroll
    for (int n = 0; n < D_STATE; n++) h[n] = 0.f;

    for (int t = 0; t < SEQ; t++) {
        int tok = b * SEQ + t;
        float dtv = dt[(size_t)tok * D_INNER + d];
        float xv  = x[(size_t)tok * D_INNER + d];
        const float* Bv = &proj[(size_t)tok * PROJ_W + DT_RANK];
        const float* Cv = Bv + D_STATE;
        float yv = 0.f;
#pragma unroll
        for (int n = 0; n < D_STATE; n++) {
            float dA = expf(dtv * A[n]);
            h[n] = dA * h[n] + dtv * Bv[n] * xv;
            yv += h[n] * Cv[n];
        }
        float zv = xz[(size_t)tok * 2 * D_INNER + D_INNER + d];
        float sz = zv / (1.f + expf(-zv));    // silu(z)
        y[(size_t)tok * D_INNER + d] = (yv + xv * Dv) * sz;
    }
}

// ---------------- host orchestration ----------------
static inline void launch_gemm(const float* A, int lda, const float* B, int ldb,
                               float* C, int ldc, int M, int N, int K, int acc)
{
    dim3 grid((N + BN - 1) / BN, M / BM);
    gemm_nt<<<grid, 256>>>(A, lda, B, ldb, C, ldc, M, N, K, acc);
}

extern "C" void kernel_launch(void* const* d_in, const int* in_sizes, int n_in,
                              void* d_out, int out_size)
{
    const int*   ids        = (const int*)d_in[0];
    const int*   mask       = (const int*)d_in[1];
    /* d_in[2] = full_loss_mask, unused */
    const float* embed      = (const float*)d_in[3];
    const float* norm_w     = (const float*)d_in[4];
    const float* in_proj_w  = (const float*)d_in[5];
    const float* conv_w     = (const float*)d_in[6];
    const float* conv_b     = (const float*)d_in[7];
    const float* x_proj_w   = (const float*)d_in[8];
    const float* dt_proj_w  = (const float*)d_in[9];
    const float* dt_proj_b  = (const float*)d_in[10];
    const float* A_log      = (const float*)d_in[11];
    const float* Dp         = (const float*)d_in[12];
    const float* out_proj_w = (const float*)d_in[13];
    const float* norm_f_w   = (const float*)d_in[14];
    float* logits = (float*)d_out;

    float *h, *hn, *xz, *x, *proj, *dt, *y;
    cudaGetSymbolAddress((void**)&h,    g_h);
    cudaGetSymbolAddress((void**)&hn,   g_hn);
    cudaGetSymbolAddress((void**)&xz,   g_xz);
    cudaGetSymbolAddress((void**)&x,    g_x);
    cudaGetSymbolAddress((void**)&proj, g_proj);
    cudaGetSymbolAddress((void**)&dt,   g_dt);
    cudaGetSymbolAddress((void**)&y,    g_y);

    // embedding gather
    gather_kernel<<<NTOK, 256>>>(ids, embed, h);

    for (int l = 0; l < N_LAYERS; l++) {
        const float* nw  = norm_w     + (size_t)l * D_MODEL;
        const float* ipw = in_proj_w  + (size_t)l * 2 * D_INNER * D_MODEL;
        const float* cw  = conv_w     + (size_t)l * D_INNER * CONV_K;
        const float* cb  = conv_b     + (size_t)l * D_INNER;
        const float* xpw = x_proj_w   + (size_t)l * PROJ_W * D_INNER;
        const float* dpw = dt_proj_w  + (size_t)l * D_INNER * DT_RANK;
        const float* dpb = dt_proj_b  + (size_t)l * D_INNER;
        const float* al  = A_log      + (size_t)l * D_INNER * D_STATE;
        const float* dd  = Dp         + (size_t)l * D_INNER;
        const float* opw = out_proj_w + (size_t)l * D_MODEL * D_INNER;

        // hn = rmsnorm(h)
        rmsnorm_kernel<<<NTOK, 256>>>(h, nw, hn);
        // xz = hn @ in_proj_w^T   [512, 3072]
        launch_gemm(hn, D_MODEL, ipw, D_MODEL, xz, 2 * D_INNER,
                    NTOK, 2 * D_INNER, D_MODEL, 0);
        // x = silu(conv(x*mask)+b) * mask   [512, 1536]
        conv_kernel<<<(NTOK * D_INNER + 255) / 256, 256>>>(xz, mask, cw, cb, x);
        // proj = x @ x_proj_w^T   [512, 80]
        launch_gemm(x, D_INNER, xpw, D_INNER, proj, PROJ_W,
                    NTOK, PROJ_W, D_INNER, 0);
        // dt_raw = dt_lo @ dt_proj_w^T   [512, 1536]  (dt_lo = proj[:, :48], lda=80)
        launch_gemm(proj, PROJ_W, dpw, DT_RANK, dt, D_INNER,
                    NTOK, D_INNER, DT_RANK, 0);
        // dt = softplus(dt_raw + b)
        dtact_kernel<<<(NTOK * D_INNER + 255) / 256, 256>>>(dt, dpb);
        // selective scan + skip + gate -> y
        scan_kernel<<<(BATCH * D_INNER + 255) / 256, 256>>>(x, dt, proj, xz, al, dd, y);
        // h += y @ out_proj_w^T   (residual via acc=1)
        launch_gemm(y, D_INNER, opw, D_INNER, h, D_MODEL,
                    NTOK, D_MODEL, D_INNER, 1);
    }

    // final norm + logits
    rmsnorm_kernel<<<NTOK, 256>>>(h, norm_f_w, hn);
    launch_gemm(hn, D_MODEL, embed, D_MODEL, logits, VOCAB,
                NTOK, VOCAB, D_MODEL, 0);
}

// round 2
// speedup vs baseline: 1.3925x; 1.3925x over previous
#include <cuda_runtime.h>
#include <math.h>

#define N_LAYERS 24
#define D_MODEL  768
#define D_INNER  1536
#define D_STATE  16
#define DT_RANK  48
#define CONV_K   4
#define VOCAB    50280
#define SEQ      8
#define BATCH    64
#define NTOK     (BATCH*SEQ)     // 512
#define LFULL    64
#define PROJ_W   (DT_RANK + 2*D_STATE)  // 80

// ---------------- scratch (alloc-free: __device__ globals) ----------------
__device__ float g_h   [NTOK * D_MODEL];
__device__ float g_hn  [NTOK * D_MODEL];
__device__ float g_xz  [NTOK * 2 * D_INNER];
__device__ float g_x   [NTOK * D_INNER];
__device__ float g_proj[NTOK * PROJ_W];
__device__ float g_dt  [NTOK * D_INNER];
__device__ float g_y   [NTOK * D_INNER];
__device__ float g_part[8 * NTOK * 768];   // split-K partials (max 8*512*80 / 2*512*768)

typedef unsigned long long ull;

// ---------------- packed f32x2 helpers ----------------
__device__ __forceinline__ ull pack_dup(float v) {
    ull r; asm("mov.b64 %0, {%1, %1};" : "=l"(r) : "f"(v)); return r;
}
__device__ __forceinline__ void ffma2(ull &d, ull a, ull b) {
    asm("fma.rn.f32x2 %0, %1, %2, %0;" : "+l"(d) : "l"(a), "l"(b));
}
__device__ __forceinline__ float2 unpack2(ull v) {
    float2 r; asm("mov.b64 {%0, %1}, %2;" : "=f"(r.x), "=f"(r.y) : "l"(v)); return r;
}

// =====================================================================
// Double-buffered NT GEMM:  C[M,N] (+)= A[M,K] * B[N,K]^T
//  - 256 threads, BK=16, thread tile TM x TN (TN = 4 or 8, TM = 2 or 4)
//  - blockIdx.z = split-K slice: uses A/B k-offset z*K, writes C + z*M*ldc
//  - M % BM == 0, K % 16 == 0; N bounds-checked (reads clamped, writes guarded)
// =====================================================================
template<int BM, int BN, int TM, int TN>
__launch_bounds__(256, 2)
__global__ void gemm_tile(const float* __restrict__ A, int lda,
                          const float* __restrict__ B, int ldb,
                          float* __restrict__ C, int ldc,
                          int M, int N, int K, int acc)
{
    constexpr int BK  = 16;
    constexpr int NTX = BN / TN;       // threads along N
    constexpr int NTN = TN / 4;        // float4 chunks per thread along N
    constexpr int NAR = (BM + 63) / 64;
    constexpr int NBR = (BN + 63) / 64;

    __shared__ float As[2][BK][BM];
    __shared__ float Bs[2][BK][BN];

    const int tid = threadIdx.x;
    const int tx  = tid % NTX;
    const int ty  = tid / NTX;
    const int bm  = blockIdx.y * BM;
    const int bn  = blockIdx.x * BN;
    const int kz  = blockIdx.z * K;            // split-K k offset
    C += (size_t)blockIdx.z * (size_t)M * ldc; // split-K output slice

    const int lr = tid >> 2;          // 0..63
    const int lc = (tid & 3) * 4;     // 0,4,8,12

    float4 pa[NAR], pb[NBR];

    auto gload = [&](int k0) {
#pragma unroll
        for (int p = 0; p < NAR; p++) {
            int r = lr + p * 64;
            if (r < BM)
                pa[p] = *reinterpret_cast<const float4*>(
                    &A[(size_t)(bm + r) * lda + kz + k0 + lc]);
        }
#pragma unroll
        for (int p = 0; p < NBR; p++) {
            int r = lr + p * 64;
            if (r < BN) {
                int n = bn + r; if (n >= N) n = N - 1;   // clamp (read only)
                pb[p] = *reinterpret_cast<const float4*>(
                    &B[(size_t)n * ldb + kz + k0 + lc]);
            }
        }
    };
    auto sstore = [&](int buf) {
#pragma unroll
        for (int p = 0; p < NAR; p++) {
            int r = lr + p * 64;
            if (r < BM) {
                As[buf][lc+0][r] = pa[p].x; As[buf][lc+1][r] = pa[p].y;
                As[buf][lc+2][r] = pa[p].z; As[buf][lc+3][r] = pa[p].w;
            }
        }
#pragma unroll
        for (int p = 0; p < NBR; p++) {
            int r = lr + p * 64;
            if (r < BN) {
                Bs[buf][lc+0][r] = pb[p].x; Bs[buf][lc+1][r] = pb[p].y;
                Bs[buf][lc+2][r] = pb[p].z; Bs[buf][lc+3][r] = pb[p].w;
            }
        }
    };

    ull accr[TM][TN/2];
#pragma unroll
    for (int i = 0; i < TM; i++)
#pragma unroll
        for (int j = 0; j < TN/2; j++) accr[i][j] = 0ull;

    gload(0); sstore(0); __syncthreads();

    const int nkb = K / BK;
    int cur = 0;
    for (int kb = 0; kb < nkb; kb++) {
        if (kb + 1 < nkb) gload((kb + 1) * BK);   // prefetch next tile to regs
#pragma unroll
        for (int k = 0; k < BK; k++) {
            float a[TM];
            if (TM == 4) {
                float4 v = *reinterpret_cast<const float4*>(&As[cur][k][ty * 4]);
                a[0]=v.x; a[1]=v.y; a[2]=v.z; a[3]=v.w;
            } else {
                float2 v = *reinterpret_cast<const float2*>(&As[cur][k][ty * 2]);
                a[0]=v.x; a[1]=v.y;
            }
            ull bfr[TN/2];
#pragma unroll
            for (int c = 0; c < NTN; c++) {
                const ull* bp = reinterpret_cast<const ull*>(&Bs[cur][k][tx*4 + c*(BN/2)]);
                bfr[c*2]   = bp[0];
                bfr[c*2+1] = bp[1];
            }
#pragma unroll
            for (int i = 0; i < TM; i++) {
                ull ai = pack_dup(a[i]);
#pragma unroll
                for (int j = 0; j < TN/2; j++) ffma2(accr[i][j], ai, bfr[j]);
            }
        }
        if (kb + 1 < nkb) { sstore(cur ^ 1); __syncthreads(); cur ^= 1; }
    }

#pragma unroll
    for (int i = 0; i < TM; i++) {
        int m = bm + ty * TM + i;
#pragma unroll
        for (int c = 0; c < NTN; c++) {
#pragma unroll
            for (int q = 0; q < 2; q++) {
                float2 v = unpack2(accr[i][c*2 + q]);
                int n = bn + tx * 4 + c * (BN/2) + q * 2;
                if (n < N) {
                    float* p = &C[(size_t)m * ldc + n];
                    if (acc) *p += v.x; else *p = v.x;
                }
                if (n + 1 < N) {
                    float* p = &C[(size_t)m * ldc + n + 1];
                    if (acc) *p += v.y; else *p = v.y;
                }
            }
        }
    }
}

// ---------------- split-K reduce: dst = (acc?dst:0) + sum_s part[s] ----------------
__global__ void reduce_split(float* __restrict__ dst, const float* __restrict__ part,
                             int nsplit, int total, int acc)
{
    int i = blockIdx.x * 256 + threadIdx.x;
    if (i >= total) return;
    float s = acc ? dst[i] : 0.f;
    for (int p = 0; p < nsplit; p++) s += part[(size_t)p * total + i];
    dst[i] = s;
}

// ---------------- embedding gather ----------------
__global__ void gather_kernel(const int* __restrict__ ids,
                              const float* __restrict__ embed,
                              float* __restrict__ h)
{
    int tok = blockIdx.x;
    int b = tok / SEQ, t = tok % SEQ;
    int id = ids[b * LFULL + t];
    const float* src = embed + (size_t)id * D_MODEL;
    for (int i = threadIdx.x; i < D_MODEL; i += 256)
        h[(size_t)tok * D_MODEL + i] = src[i];
}

// ---------------- rmsnorm (one block per token) ----------------
__global__ void rmsnorm_kernel(const float* __restrict__ in,
                               const float* __restrict__ w,
                               float* __restrict__ out)
{
    int tok = blockIdx.x;
    __shared__ float red[256];
    const float* row = in + (size_t)tok * D_MODEL;
    float s = 0.f;
    for (int i = threadIdx.x; i < D_MODEL; i += 256) { float v = row[i]; s += v * v; }
    red[threadIdx.x] = s;
    __syncthreads();
    for (int st = 128; st > 0; st >>= 1) {
        if (threadIdx.x < st) red[threadIdx.x] += red[threadIdx.x + st];
        __syncthreads();
    }
    float inv = rsqrtf(red[0] / (float)D_MODEL + 1e-5f);
    for (int i = threadIdx.x; i < D_MODEL; i += 256)
        out[(size_t)tok * D_MODEL + i] = row[i] * inv * w[i];
}

// ---------------- causal depthwise conv (K=4) + bias + silu + mask ----------------
__global__ void conv_kernel(const float* __restrict__ xz,
                            const int* __restrict__ mask,
                            const float* __restrict__ cw,
                            const float* __restrict__ cb,
                            float* __restrict__ xout)
{
    int gid = blockIdx.x * blockDim.x + threadIdx.x;
    if (gid >= NTOK * D_INNER) return;
    int d = gid % D_INNER;
    int tok = gid / D_INNER;
    int b = tok / SEQ, t = tok % SEQ;

    float acc = cb[d];
#pragma unroll
    for (int j = 0; j < CONV_K; j++) {
        int tt = t - (CONV_K - 1) + j;
        if (tt >= 0) {
            float mv = (float)mask[b * LFULL + tt];
            acc += cw[d * CONV_K + j] * xz[(size_t)(b * SEQ + tt) * 2 * D_INNER + d] * mv;
        }
    }
    float s = acc / (1.f + expf(-acc));       // silu
    float mv = (float)mask[b * LFULL + t];
    xout[gid] = s * mv;
}

// ---------------- selective scan (fused dt bias+softplus) + skip + gate ----------------
__global__ void scan_kernel(const float* __restrict__ x,
                            const float* __restrict__ dtraw,
                            const float* __restrict__ dtb,
                            const float* __restrict__ proj,
                            const float* __restrict__ xz,
                            const float* __restrict__ A_log,
                            const float* __restrict__ Dp,
                            float* __restrict__ y)
{
    int gid = blockIdx.x * blockDim.x + threadIdx.x;
    if (gid >= BATCH * D_INNER) return;
    int d = gid % D_INNER;
    int b = gid / D_INNER;

    float A[D_STATE];
#pragma unroll
    for (int n = 0; n < D_STATE; n++) A[n] = -expf(A_log[d * D_STATE + n]);
    float Dv = Dp[d];
    float bias = dtb[d];

    float h[D_STATE];
#pragma unroll
    for (int n = 0; n < D_STATE; n++) h[n] = 0.f;

    for (int t = 0; t < SEQ; t++) {
        int tok = b * SEQ + t;
        float v = dtraw[(size_t)tok * D_INNER + d] + bias;
        float dtv = (v > 20.f) ? v : log1pf(expf(v));      // softplus
        float xv  = x[(size_t)tok * D_INNER + d];
        const float* Bv = &proj[(size_t)tok * PROJ_W + DT_RANK];
        const float* Cv = Bv + D_STATE;
        float yv = 0.f;
#pragma unroll
        for (int n = 0; n < D_STATE; n++) {
            float dA = expf(dtv * A[n]);
            h[n] = dA * h[n] + dtv * Bv[n] * xv;
            yv += h[n] * Cv[n];
        }
        float zv = xz[(size_t)tok * 2 * D_INNER + D_INNER + d];
        float sz = zv / (1.f + expf(-zv));    // silu(z)
        y[(size_t)tok * D_INNER + d] = (yv + xv * Dv) * sz;
    }
}

// ---------------- host orchestration ----------------
extern "C" void kernel_launch(void* const* d_in, const int* in_sizes, int n_in,
                              void* d_out, int out_size)
{
    const int*   ids        = (const int*)d_in[0];
    const int*   mask       = (const int*)d_in[1];
    /* d_in[2] = full_loss_mask, unused */
    const float* embed      = (const float*)d_in[3];
    const float* norm_w     = (const float*)d_in[4];
    const float* in_proj_w  = (const float*)d_in[5];
    const float* conv_w     = (const float*)d_in[6];
    const float* conv_b     = (const float*)d_in[7];
    const float* x_proj_w   = (const float*)d_in[8];
    const float* dt_proj_w  = (const float*)d_in[9];
    const float* dt_proj_b  = (const float*)d_in[10];
    const float* A_log      = (const float*)d_in[11];
    const float* Dp         = (const float*)d_in[12];
    const float* out_proj_w = (const float*)d_in[13];
    const float* norm_f_w   = (const float*)d_in[14];
    float* logits = (float*)d_out;

    float *h, *hn, *xz, *x, *proj, *dt, *y, *part;
    cudaGetSymbolAddress((void**)&h,    g_h);
    cudaGetSymbolAddress((void**)&hn,   g_hn);
    cudaGetSymbolAddress((void**)&xz,   g_xz);
    cudaGetSymbolAddress((void**)&x,    g_x);
    cudaGetSymbolAddress((void**)&proj, g_proj);
    cudaGetSymbolAddress((void**)&dt,   g_dt);
    cudaGetSymbolAddress((void**)&y,    g_y);
    cudaGetSymbolAddress((void**)&part, g_part);

    gather_kernel<<<NTOK, 256>>>(ids, embed, h);

    for (int l = 0; l < N_LAYERS; l++) {
        const float* nw  = norm_w     + (size_t)l * D_MODEL;
        const float* ipw = in_proj_w  + (size_t)l * 2 * D_INNER * D_MODEL;
        const float* cw  = conv_w     + (size_t)l * D_INNER * CONV_K;
        const float* cb  = conv_b     + (size_t)l * D_INNER;
        const float* xpw = x_proj_w   + (size_t)l * PROJ_W * D_INNER;
        const float* dpw = dt_proj_w  + (size_t)l * D_INNER * DT_RANK;
        const float* dpb = dt_proj_b  + (size_t)l * D_INNER;
        const float* al  = A_log      + (size_t)l * D_INNER * D_STATE;
        const float* dd  = Dp         + (size_t)l * D_INNER;
        const float* opw = out_proj_w + (size_t)l * D_MODEL * D_INNER;

        // hn = rmsnorm(h)
        rmsnorm_kernel<<<NTOK, 256>>>(h, nw, hn);

        // xz = hn @ in_proj_w^T   [512, 3072]   (384 blocks)
        gemm_tile<32,128,4,4><<<dim3(2*D_INNER/128, NTOK/32, 1), 256>>>(
            hn, D_MODEL, ipw, D_MODEL, xz, 2*D_INNER, NTOK, 2*D_INNER, D_MODEL, 0);

        // x = silu(conv(x*mask)+b)*mask  [512, 1536]
        conv_kernel<<<(NTOK*D_INNER + 255)/256, 256>>>(xz, mask, cw, cb, x);

        // proj = x @ x_proj_w^T  [512, 80]  split-K 8 (256 blocks) + reduce
        gemm_tile<32,64,2,4><<<dim3(2, NTOK/32, 8), 256>>>(
            x, D_INNER, xpw, D_INNER, part, PROJ_W, NTOK, PROJ_W, D_INNER/8, 0);
        reduce_split<<<(NTOK*PROJ_W + 255)/256, 256>>>(proj, part, 8, NTOK*PROJ_W, 0);

        // dt_raw = proj[:, :48] @ dt_proj_w^T  [512, 1536]  (192 blocks)
        gemm_tile<32,128,4,4><<<dim3(D_INNER/128, NTOK/32, 1), 256>>>(
            proj, PROJ_W, dpw, DT_RANK, dt, D_INNER, NTOK, D_INNER, DT_RANK, 0);

        // selective scan (softplus fused) + skip + gate -> y
        scan_kernel<<<(BATCH*D_INNER + 255)/256, 256>>>(x, dt, dpb, proj, xz, al, dd, y);

        // h += y @ out_proj_w^T  split-K 2 (192 blocks) + accumulating reduce
        gemm_tile<64,64,4,4><<<dim3(D_MODEL/64, NTOK/64, 2), 256>>>(
            y, D_INNER, opw, D_INNER, part, D_MODEL, NTOK, D_MODEL, D_INNER/2, 0);
        reduce_split<<<(NTOK*D_MODEL + 255)/256, 256>>>(h, part, 2, NTOK*D_MODEL, 1);
    }

    // final norm + logits [512, 50280]  (3144 blocks)
    rmsnorm_kernel<<<NTOK, 256>>>(h, norm_f_w, hn);
    gemm_tile<64,128,4,8><<<dim3((VOCAB + 127)/128, NTOK/64, 1), 256>>>(
        hn, D_MODEL, embed, D_MODEL, logits, VOCAB, NTOK, VOCAB, D_MODEL, 0);
}